// round 5
// baseline (speedup 1.0000x reference)
#include <cuda_runtime.h>
#include <math.h>
#include <stdint.h>

#define CDIV(a,b) (((a)+(b)-1)/(b))

static const int B  = 32;
static const int C  = 256;
static const int NZ = 225;   // 15*15
static const int NX = 961;   // 31*31
static const int KDIM = 2304; // C*9

// ---------------- scratch (device globals; no cudaMalloc allowed) ----------
__device__ float g_attnA[32 * 256 * 256];
__device__ float g_attnB[32 * 256 * 256];
__device__ float g_featZ[32 * 256 * 225];
__device__ float g_featX[32 * 256 * 961];
__device__ float g_off  [32 * 18  * 961];
__device__ float g_col  [2304 * 32 * 1024];   // padded im2col (302 MB)
__device__ float g_wr   [256 * 2304];         // tf32-rounded weights
__device__ float g_hi   [32 * 256 * 961];     // tf32 split hi (31.5 MB)
__device__ float g_lo   [32 * 256 * 961];     // tf32 split lo (31.5 MB)

// ======================= PTX helpers =======================================
__device__ __forceinline__ uint32_t smem_u32(const void* p) {
    uint32_t a;
    asm("{ .reg .u64 t; cvta.to.shared.u64 t, %1; cvt.u32.u64 %0, t; }" : "=r"(a) : "l"(p));
    return a;
}
__device__ __forceinline__ void cpa16(uint32_t dst, const void* src) {
    asm volatile("cp.async.cg.shared.global [%0], [%1], 16;" :: "r"(dst), "l"(src));
}
__device__ __forceinline__ float round_tf32(float v) {
    uint32_t r;
    asm("cvt.rna.tf32.f32 %0, %1;" : "=r"(r) : "f"(v));
    return __uint_as_float(r);
}
__device__ __forceinline__ void mma_tf32(float& c0, float& c1, float& c2, float& c3,
                                         uint32_t a0, uint32_t a1, uint32_t a2, uint32_t a3,
                                         uint32_t b0, uint32_t b1) {
    asm volatile(
        "mma.sync.aligned.m16n8k8.row.col.f32.tf32.tf32.f32 "
        "{%0,%1,%2,%3},{%4,%5,%6,%7},{%8,%9},{%0,%1,%2,%3};"
        : "+f"(c0), "+f"(c1), "+f"(c2), "+f"(c3)
        : "r"(a0), "r"(a1), "r"(a2), "r"(a3), "r"(b0), "r"(b1));
}

// ---------------------------------------------------------------------------
// split input into tf32 hi/lo pair (for 3xTF32 gram)
// ---------------------------------------------------------------------------
__global__ __launch_bounds__(256) void splitf_kernel(const float* __restrict__ in,
                                                     float* __restrict__ hi,
                                                     float* __restrict__ lo, int n) {
    int i = blockIdx.x * 256 + threadIdx.x;
    if (i < n) {
        float v = in[i];
        float h = round_tf32(v);
        hi[i] = h;
        lo[i] = round_tf32(v - h);
    }
}

// ---------------------------------------------------------------------------
// gram via 3xTF32: E[b] = F[b] * F[b]^T  (fp32-grade accuracy)
// CTA 128x128, BK=16, 8 warps (2M x 4N)
// ---------------------------------------------------------------------------
__global__ __launch_bounds__(256) void gram_mma3_kernel(const float* __restrict__ hi,
                                                        const float* __restrict__ lo,
                                                        float* __restrict__ E, int K) {
    __shared__ float Ah[128 * 20], Al[128 * 20], Bh[128 * 20], Bl[128 * 20];
    int b = blockIdx.z;
    int c0 = blockIdx.y * 128, d0 = blockIdx.x * 128;
    const size_t fb = (size_t)b * C * K;
    int tid = threadIdx.x;
    int wid = tid >> 5, lane = tid & 31;
    int g = lane >> 2, t = lane & 3;
    int warpM = wid >> 2, warpN = wid & 3;

    float acc[4][4][4];
#pragma unroll
    for (int i = 0; i < 4; i++)
#pragma unroll
        for (int j = 0; j < 4; j++)
#pragma unroll
            for (int r = 0; r < 4; r++) acc[i][j][r] = 0.f;

    int ITERS = (K + 15) / 16;
    for (int it = 0; it < ITERS; it++) {
        int k0 = it * 16;
        __syncthreads();
#pragma unroll
        for (int i = 0; i < 8; i++) {
            int idx = tid + i * 256;
            int row = idx >> 4, kk = idx & 15;
            int k = k0 + kk;
            float ha = 0.f, la = 0.f, hb = 0.f, lb = 0.f;
            if (k < K) {
                size_t ia = fb + (size_t)(c0 + row) * K + k;
                size_t ib = fb + (size_t)(d0 + row) * K + k;
                ha = hi[ia]; la = lo[ia];
                hb = hi[ib]; lb = lo[ib];
            }
            Ah[row * 20 + kk] = ha; Al[row * 20 + kk] = la;
            Bh[row * 20 + kk] = hb; Bl[row * 20 + kk] = lb;
        }
        __syncthreads();
#pragma unroll
        for (int ks = 0; ks < 2; ks++) {
            int kb = ks * 8;
            uint32_t ah[4][4], al[4][4];
#pragma unroll
            for (int mt = 0; mt < 4; mt++) {
                int m = warpM * 64 + mt * 16 + g;
                ah[mt][0] = __float_as_uint(Ah[m * 20 + kb + t]);
                ah[mt][1] = __float_as_uint(Ah[(m + 8) * 20 + kb + t]);
                ah[mt][2] = __float_as_uint(Ah[m * 20 + kb + t + 4]);
                ah[mt][3] = __float_as_uint(Ah[(m + 8) * 20 + kb + t + 4]);
                al[mt][0] = __float_as_uint(Al[m * 20 + kb + t]);
                al[mt][1] = __float_as_uint(Al[(m + 8) * 20 + kb + t]);
                al[mt][2] = __float_as_uint(Al[m * 20 + kb + t + 4]);
                al[mt][3] = __float_as_uint(Al[(m + 8) * 20 + kb + t + 4]);
            }
            uint32_t bh[4][2], bl[4][2];
#pragma unroll
            for (int nt = 0; nt < 4; nt++) {
                int n = warpN * 32 + nt * 8 + g;
                bh[nt][0] = __float_as_uint(Bh[n * 20 + kb + t]);
                bh[nt][1] = __float_as_uint(Bh[n * 20 + kb + t + 4]);
                bl[nt][0] = __float_as_uint(Bl[n * 20 + kb + t]);
                bl[nt][1] = __float_as_uint(Bl[n * 20 + kb + t + 4]);
            }
#pragma unroll
            for (int mt = 0; mt < 4; mt++)
#pragma unroll
                for (int nt = 0; nt < 4; nt++) {
                    mma_tf32(acc[mt][nt][0], acc[mt][nt][1], acc[mt][nt][2], acc[mt][nt][3],
                             ah[mt][0], ah[mt][1], ah[mt][2], ah[mt][3],
                             bh[nt][0], bh[nt][1]);
                    mma_tf32(acc[mt][nt][0], acc[mt][nt][1], acc[mt][nt][2], acc[mt][nt][3],
                             ah[mt][0], ah[mt][1], ah[mt][2], ah[mt][3],
                             bl[nt][0], bl[nt][1]);
                    mma_tf32(acc[mt][nt][0], acc[mt][nt][1], acc[mt][nt][2], acc[mt][nt][3],
                             al[mt][0], al[mt][1], al[mt][2], al[mt][3],
                             bh[nt][0], bh[nt][1]);
                }
        }
    }
    float* Eb = E + (size_t)b * C * C;
#pragma unroll
    for (int mt = 0; mt < 4; mt++) {
        int m = c0 + warpM * 64 + mt * 16 + g;
#pragma unroll
        for (int nt = 0; nt < 4; nt++) {
            int n = d0 + warpN * 32 + nt * 8 + t * 2;
            Eb[(size_t)m * C + n]           = acc[mt][nt][0];
            Eb[(size_t)m * C + n + 1]       = acc[mt][nt][1];
            Eb[(size_t)(m + 8) * C + n]     = acc[mt][nt][2];
            Eb[(size_t)(m + 8) * C + n + 1] = acc[mt][nt][3];
        }
    }
}

// ---------------------------------------------------------------------------
// softmax of (rowmax - e) == exp(rowmin - e)/sum
// ---------------------------------------------------------------------------
__global__ __launch_bounds__(256) void attn_softmax_kernel(float* __restrict__ E) {
    int row = blockIdx.x;
    float* e = E + (size_t)row * 256;
    int t = threadIdx.x;
    float v = e[t];
    __shared__ float red[256];
    red[t] = v;
    __syncthreads();
    for (int s = 128; s > 0; s >>= 1) {
        if (t < s) red[t] = fminf(red[t], red[t + s]);
        __syncthreads();
    }
    float emin = red[0];
    __syncthreads();
    float p = expf(emin - v);
    red[t] = p;
    __syncthreads();
    for (int s = 128; s > 0; s >>= 1) {
        if (t < s) red[t] += red[t + s];
        __syncthreads();
    }
    e[t] = p / red[0];
}

// ---------------------------------------------------------------------------
// cam_use via tf32 MMA: O[b] = gamma * A[b] @ F[b] + F[b]
// CTA 128x128, BK=16, K=256, 8 warps (2M x 4N)
// ---------------------------------------------------------------------------
__global__ __launch_bounds__(256) void camuse_mma_kernel(const float* __restrict__ A,
                                                         const float* __restrict__ F,
                                                         float* __restrict__ O, int N,
                                                         const float* __restrict__ gamma) {
    __shared__ float sA[128 * 20];
    __shared__ float sB[16 * 136];
    int b = blockIdx.z;
    int m0 = blockIdx.y * 128, n0 = blockIdx.x * 128;
    const float* Ab = A + (size_t)b * C * C;
    const float* Fb = F + (size_t)b * C * N;
    int tid = threadIdx.x;
    int wid = tid >> 5, lane = tid & 31;
    int g = lane >> 2, t = lane & 3;
    int warpM = wid >> 2, warpN = wid & 3;

    float acc[4][4][4];
#pragma unroll
    for (int i = 0; i < 4; i++)
#pragma unroll
        for (int j = 0; j < 4; j++)
#pragma unroll
            for (int r = 0; r < 4; r++) acc[i][j][r] = 0.f;

    for (int it = 0; it < 16; it++) {
        int k0 = it * 16;
        __syncthreads();
#pragma unroll
        for (int i = 0; i < 8; i++) {
            int idx = tid + i * 256;
            int row = idx >> 4, kk = idx & 15;
            sA[row * 20 + kk] = round_tf32(Ab[(size_t)(m0 + row) * C + k0 + kk]);
        }
#pragma unroll
        for (int i = 0; i < 8; i++) {
            int idx = tid + i * 256;
            int r = idx >> 7, cc = idx & 127;
            int n = n0 + cc;
            sB[r * 136 + cc] = (n < N) ? round_tf32(Fb[(size_t)(k0 + r) * N + n]) : 0.f;
        }
        __syncthreads();
#pragma unroll
        for (int ks = 0; ks < 2; ks++) {
            int kb = ks * 8;
            uint32_t af[4][4];
#pragma unroll
            for (int mt = 0; mt < 4; mt++) {
                int m = warpM * 64 + mt * 16 + g;
                af[mt][0] = __float_as_uint(sA[m * 20 + kb + t]);
                af[mt][1] = __float_as_uint(sA[(m + 8) * 20 + kb + t]);
                af[mt][2] = __float_as_uint(sA[m * 20 + kb + t + 4]);
                af[mt][3] = __float_as_uint(sA[(m + 8) * 20 + kb + t + 4]);
            }
            uint32_t bf[4][2];
#pragma unroll
            for (int nt = 0; nt < 4; nt++) {
                int n = warpN * 32 + nt * 8 + g;
                bf[nt][0] = __float_as_uint(sB[(kb + t) * 136 + n]);
                bf[nt][1] = __float_as_uint(sB[(kb + t + 4) * 136 + n]);
            }
#pragma unroll
            for (int mt = 0; mt < 4; mt++)
#pragma unroll
                for (int nt = 0; nt < 4; nt++)
                    mma_tf32(acc[mt][nt][0], acc[mt][nt][1], acc[mt][nt][2], acc[mt][nt][3],
                             af[mt][0], af[mt][1], af[mt][2], af[mt][3],
                             bf[nt][0], bf[nt][1]);
        }
    }
    float gm = gamma[0];
#pragma unroll
    for (int mt = 0; mt < 4; mt++) {
        int m = m0 + warpM * 64 + mt * 16 + g;
#pragma unroll
        for (int nt = 0; nt < 4; nt++) {
            int n = n0 + warpN * 32 + nt * 8 + t * 2;
            if (n < N) {
                O[((size_t)b * C + m) * N + n] = gm * acc[mt][nt][0] + Fb[(size_t)m * N + n];
                O[((size_t)b * C + m + 8) * N + n] = gm * acc[mt][nt][2] + Fb[(size_t)(m + 8) * N + n];
                if (n + 1 < N) {
                    O[((size_t)b * C + m) * N + n + 1] = gm * acc[mt][nt][1] + Fb[(size_t)m * N + n + 1];
                    O[((size_t)b * C + m + 8) * N + n + 1] = gm * acc[mt][nt][3] + Fb[(size_t)(m + 8) * N + n + 1];
                }
            }
        }
    }
}

// ---------------------------------------------------------------------------
// offset conv: 3x3, C -> 18, pad 1.  All 18 channels per block, 2 px/thread.
// grid (CDIV(N,256), B), 128 threads
// ---------------------------------------------------------------------------
__global__ __launch_bounds__(128) void offconv2_kernel(const float* __restrict__ feat,
                                                       const float* __restrict__ woff,
                                                       const float* __restrict__ boff,
                                                       float* __restrict__ off,
                                                       int H, int W) {
    __shared__ float sw[32 * 162];   // [cc][tap][ch]
    int b = blockIdx.y;
    int N = H * W;
    int tid = threadIdx.x;
    int p0 = blockIdx.x * 256 + tid;
    int p1 = p0 + 128;

    int idx0[9], idx1[9];
#pragma unroll
    for (int tap = 0; tap < 9; tap++) { idx0[tap] = -1; idx1[tap] = -1; }
    if (p0 < N) {
        int h = p0 / W, w = p0 % W;
#pragma unroll
        for (int tap = 0; tap < 9; tap++) {
            int y = h + tap / 3 - 1, x = w + tap % 3 - 1;
            if ((unsigned)y < (unsigned)H && (unsigned)x < (unsigned)W)
                idx0[tap] = y * W + x;
        }
    }
    if (p1 < N) {
        int h = p1 / W, w = p1 % W;
#pragma unroll
        for (int tap = 0; tap < 9; tap++) {
            int y = h + tap / 3 - 1, x = w + tap % 3 - 1;
            if ((unsigned)y < (unsigned)H && (unsigned)x < (unsigned)W)
                idx1[tap] = y * W + x;
        }
    }

    float acc0[18], acc1[18];
#pragma unroll
    for (int ch = 0; ch < 18; ch++) { acc0[ch] = 0.f; acc1[ch] = 0.f; }

    for (int c0 = 0; c0 < C; c0 += 32) {
        __syncthreads();
        for (int i = tid; i < 32 * 162; i += 128) {
            int cc = i / 162, r = i % 162;
            int tap = r / 18, ch = r % 18;
            sw[i] = woff[(size_t)ch * 2304 + (c0 + cc) * 9 + tap];
        }
        __syncthreads();
        for (int cc = 0; cc < 32; cc++) {
            const float* fc = feat + ((size_t)b * C + c0 + cc) * N;
            const float* swc = &sw[cc * 162];
#pragma unroll
            for (int tap = 0; tap < 9; tap++) {
                float f0 = (idx0[tap] >= 0) ? fc[idx0[tap]] : 0.f;
                float f1 = (idx1[tap] >= 0) ? fc[idx1[tap]] : 0.f;
                const float* wp = swc + tap * 18;
#pragma unroll
                for (int ch = 0; ch < 18; ch++) {
                    float w = wp[ch];
                    acc0[ch] += w * f0;
                    acc1[ch] += w * f1;
                }
            }
        }
    }

#pragma unroll
    for (int ch = 0; ch < 18; ch++) {
        float bias = boff[ch];
        if (p0 < N) off[((size_t)b * 18 + ch) * N + p0] = acc0[ch] + bias;
        if (p1 < N) off[((size_t)b * 18 + ch) * N + p1] = acc1[ch] + bias;
    }
}

// ---------------------------------------------------------------------------
// bilinear deform sampling -> padded im2col, tf32-rounded values
// ---------------------------------------------------------------------------
__global__ __launch_bounds__(128) void sample_kernel(const float* __restrict__ feat,
                                                     const float* __restrict__ off,
                                                     float* __restrict__ col,
                                                     int H, int W, int Npad, int NtotPad) {
    int N = H * W;
    int b = blockIdx.z, k = blockIdx.y;
    int n = blockIdx.x * 128 + threadIdx.x;
    if (n >= N) return;
    int h = n / W, w = n % W;
    int ky = k / 3, kx = k % 3;
    float oy = off[((size_t)b * 18 + 2 * k) * N + n];
    float ox = off[((size_t)b * 18 + 2 * k + 1) * N + n];
    float py = (float)(h + ky - 1) + oy;
    float px = (float)(w + kx - 1) + ox;
    float y0f = floorf(py), x0f = floorf(px);
    float ly = py - y0f, lx = px - x0f;
    float Hm1 = (float)(H - 1), Wm1 = (float)(W - 1);

    float vy0 = (y0f >= 0.f && y0f <= Hm1) ? (1.f - ly) : 0.f;
    float vy1 = (y0f + 1.f >= 0.f && y0f + 1.f <= Hm1) ? ly : 0.f;
    float vx0 = (x0f >= 0.f && x0f <= Wm1) ? (1.f - lx) : 0.f;
    float vx1 = (x0f + 1.f >= 0.f && x0f + 1.f <= Wm1) ? lx : 0.f;
    int y0 = (int)fminf(fmaxf(y0f, 0.f), Hm1);
    int y1 = (int)fminf(fmaxf(y0f + 1.f, 0.f), Hm1);
    int x0 = (int)fminf(fmaxf(x0f, 0.f), Wm1);
    int x1 = (int)fminf(fmaxf(x0f + 1.f, 0.f), Wm1);

    int i00 = y0 * W + x0, i01 = y0 * W + x1, i10 = y1 * W + x0, i11 = y1 * W + x1;
    float w00 = vy0 * vx0, w01 = vy0 * vx1, w10 = vy1 * vx0, w11 = vy1 * vx1;

    const float* fb = feat + (size_t)b * C * N;
    float* cp = col + (size_t)k * NtotPad + (size_t)b * Npad + n;
    const size_t cstride = (size_t)9 * NtotPad;
    for (int c = 0; c < C; c++) {
        const float* fc = fb + (size_t)c * N;
        float v = w00 * fc[i00] + w01 * fc[i01] + w10 * fc[i10] + w11 * fc[i11];
        cp[(size_t)c * cstride] = round_tf32(v);
    }
}

// ---------------------------------------------------------------------------
// round W to tf32 once per scale
// ---------------------------------------------------------------------------
__global__ __launch_bounds__(256) void wround_kernel(const float* __restrict__ in,
                                                     float* __restrict__ out, int n) {
    int i = blockIdx.x * 256 + threadIdx.x;
    if (i < n) out[i] = round_tf32(in[i]);
}

// ---------------------------------------------------------------------------
// tf32 mma.sync GEMM:  out = W[256 x 2304] @ col[2304 x NtotPad]
// CTA 128x128, BK=16, 8 warps (2M x 4N), double-buffer cp.async
// ---------------------------------------------------------------------------
#define A_STRIDE 20
#define B_STRIDE 136

__global__ __launch_bounds__(256) void dconv_mma_kernel(const float* __restrict__ Wm,
                                                        const float* __restrict__ Bc,
                                                        float* __restrict__ out,
                                                        int Nsp, int NtotPad, int shift) {
    __shared__ float sA[2][128 * A_STRIDE];
    __shared__ float sB[2][16 * B_STRIDE];

    int tid = threadIdx.x;
    int wid = tid >> 5, lane = tid & 31;
    int g = lane >> 2, t = lane & 3;
    int warpM = wid >> 2;
    int warpN = wid & 3;

    int n0 = blockIdx.x * 128;
    int m0 = blockIdx.y * 128;
    int bb = n0 >> shift;
    int nl0 = n0 & ((1 << shift) - 1);

    uint32_t sAu = smem_u32(&sA[0][0]);
    uint32_t sBu = smem_u32(&sB[0][0]);

    auto load_stage = [&](int stg, int k0) {
        uint32_t aBase = sAu + stg * (128 * A_STRIDE * 4);
        uint32_t bBase = sBu + stg * (16 * B_STRIDE * 4);
#pragma unroll
        for (int i = 0; i < 2; i++) {
            int q = tid + i * 256;
            int row = q >> 2, c16 = q & 3;
            cpa16(aBase + (row * A_STRIDE + c16 * 4) * 4,
                  Wm + (size_t)(m0 + row) * KDIM + k0 + c16 * 4);
        }
#pragma unroll
        for (int i = 0; i < 2; i++) {
            int q = tid + i * 256;
            int row = q >> 5, c = q & 31;
            cpa16(bBase + (row * B_STRIDE + c * 4) * 4,
                  Bc + (size_t)(k0 + row) * NtotPad + n0 + c * 4);
        }
    };

    float acc[4][4][4];
#pragma unroll
    for (int i = 0; i < 4; i++)
#pragma unroll
        for (int j = 0; j < 4; j++)
#pragma unroll
            for (int r = 0; r < 4; r++) acc[i][j][r] = 0.f;

    const int ITERS = KDIM / 16;   // 144
    load_stage(0, 0);
    asm volatile("cp.async.commit_group;" ::: "memory");

    for (int it = 0; it < ITERS; ++it) {
        int cur = it & 1;
        if (it + 1 < ITERS) load_stage(cur ^ 1, (it + 1) * 16);
        asm volatile("cp.async.commit_group;" ::: "memory");
        asm volatile("cp.async.wait_group 1;" ::: "memory");
        __syncthreads();

        const float* A0 = &sA[cur][0];
        const float* B0 = &sB[cur][0];
#pragma unroll
        for (int ks = 0; ks < 2; ks++) {
            int kb = ks * 8;
            uint32_t af[4][4];
#pragma unroll
            for (int mt = 0; mt < 4; mt++) {
                int m = warpM * 64 + mt * 16 + g;
                af[mt][0] = __float_as_uint(A0[m * A_STRIDE + kb + t]);
                af[mt][1] = __float_as_uint(A0[(m + 8) * A_STRIDE + kb + t]);
                af[mt][2] = __float_as_uint(A0[m * A_STRIDE + kb + t + 4]);
                af[mt][3] = __float_as_uint(A0[(m + 8) * A_STRIDE + kb + t + 4]);
            }
            uint32_t bf[4][2];
#pragma unroll
            for (int nt = 0; nt < 4; nt++) {
                int n = warpN * 32 + nt * 8 + g;
                bf[nt][0] = __float_as_uint(B0[(kb + t) * B_STRIDE + n]);
                bf[nt][1] = __float_as_uint(B0[(kb + t + 4) * B_STRIDE + n]);
            }
#pragma unroll
            for (int mt = 0; mt < 4; mt++)
#pragma unroll
                for (int nt = 0; nt < 4; nt++)
                    mma_tf32(acc[mt][nt][0], acc[mt][nt][1], acc[mt][nt][2], acc[mt][nt][3],
                             af[mt][0], af[mt][1], af[mt][2], af[mt][3],
                             bf[nt][0], bf[nt][1]);
        }
        __syncthreads();
    }

#pragma unroll
    for (int mt = 0; mt < 4; mt++) {
        int m = m0 + warpM * 64 + mt * 16 + g;
        float* r0 = out + ((size_t)bb * C + m) * Nsp;
        float* r1 = out + ((size_t)bb * C + m + 8) * Nsp;
#pragma unroll
        for (int nt = 0; nt < 4; nt++) {
            int n = nl0 + warpN * 32 + nt * 8 + t * 2;
            if (n < Nsp) {
                r0[n] = acc[mt][nt][0];
                r1[n] = acc[mt][nt][2];
                if (n + 1 < Nsp) {
                    r0[n + 1] = acc[mt][nt][1];
                    r1[n + 1] = acc[mt][nt][3];
                }
            }
        }
    }
}

// ---------------------------------------------------------------------------
extern "C" void kernel_launch(void* const* d_in, const int* in_sizes, int n_in,
                              void* d_out, int out_size) {
    const float *Z[3], *X[3], *OW[3], *OB[3], *DW[3], *G[3];
    int nz = 0, nx = 0, nw = 0, nb = 0, nd = 0, ng = 0;
    for (int i = 0; i < n_in; i++) {
        switch (in_sizes[i]) {
            case 1843200: Z[nz++]  = (const float*)d_in[i]; break;
            case 7872512: X[nx++]  = (const float*)d_in[i]; break;
            case 41472:   OW[nw++] = (const float*)d_in[i]; break;
            case 18:      OB[nb++] = (const float*)d_in[i]; break;
            case 589824:  DW[nd++] = (const float*)d_in[i]; break;
            case 1:       G[ng++]  = (const float*)d_in[i]; break;
            default: break;
        }
    }

    float *attnA, *attnB, *featZ, *featX, *offb, *colb, *wrb, *hib, *lob;
    cudaGetSymbolAddress((void**)&attnA, g_attnA);
    cudaGetSymbolAddress((void**)&attnB, g_attnB);
    cudaGetSymbolAddress((void**)&featZ, g_featZ);
    cudaGetSymbolAddress((void**)&featX, g_featX);
    cudaGetSymbolAddress((void**)&offb,  g_off);
    cudaGetSymbolAddress((void**)&colb,  g_col);
    cudaGetSymbolAddress((void**)&wrb,   g_wr);
    cudaGetSymbolAddress((void**)&hib,   g_hi);
    cudaGetSymbolAddress((void**)&lob,   g_lo);

    float* outZ = (float*)d_out;
    float* outX = outZ + (size_t)3 * B * C * NZ;

    const int NPAD_Z = 256,  SH_Z = 8;
    const int NPAD_X = 1024, SH_X = 10;
    const int NTOT_Z = B * NPAD_Z;   // 8192
    const int NTOT_X = B * NPAD_X;   // 32768
    const int NEL_Z = B * C * NZ;    // 1843200
    const int NEL_X = B * C * NX;    // 7872512

    for (int i = 0; i < 3; i++) {
        // --- channel attention (gram via 3xTF32) ---
        splitf_kernel<<<CDIV(NEL_Z, 256), 256>>>(Z[i], hib, lob, NEL_Z);
        gram_mma3_kernel<<<dim3(2, 2, B), 256>>>(hib, lob, attnA, NZ);
        attn_softmax_kernel<<<B * C, 256>>>(attnA);
        splitf_kernel<<<CDIV(NEL_X, 256), 256>>>(X[i], hib, lob, NEL_X);
        gram_mma3_kernel<<<dim3(2, 2, B), 256>>>(hib, lob, attnB, NX);
        attn_softmax_kernel<<<B * C, 256>>>(attnB);

        // --- cam_use (cross attention) via tf32 MMA ---
        camuse_mma_kernel<<<dim3(2, 2, B), 256>>>(attnB, Z[i], featZ, NZ, G[i]);
        camuse_mma_kernel<<<dim3(8, 2, B), 256>>>(attnA, X[i], featX, NX, G[i]);

        wround_kernel<<<CDIV(256 * KDIM, 256), 256>>>(DW[i], wrb, 256 * KDIM);

        // --- z branch ---
        offconv2_kernel<<<dim3(CDIV(NZ, 256), B), 128>>>(featZ, OW[i], OB[i], offb, 15, 15);
        sample_kernel<<<dim3(CDIV(NZ, 128), 9, B), 128>>>(featZ, offb, colb, 15, 15, NPAD_Z, NTOT_Z);
        dconv_mma_kernel<<<dim3(NTOT_Z / 128, 2), 256>>>(wrb, colb,
                                                         outZ + (size_t)i * B * C * NZ,
                                                         NZ, NTOT_Z, SH_Z);
        // --- x branch ---
        offconv2_kernel<<<dim3(CDIV(NX, 256), B), 128>>>(featX, OW[i], OB[i], offb, 31, 31);
        sample_kernel<<<dim3(CDIV(NX, 128), 9, B), 128>>>(featX, offb, colb, 31, 31, NPAD_X, NTOT_X);
        dconv_mma_kernel<<<dim3(NTOT_X / 128, 2), 256>>>(wrb, colb,
                                                         outX + (size_t)i * B * C * NX,
                                                         NX, NTOT_X, SH_X);
    }
    (void)out_size;
}

// round 6
// speedup vs baseline: 1.0568x; 1.0568x over previous
#include <cuda_runtime.h>
#include <math.h>
#include <stdint.h>

#define CDIV(a,b) (((a)+(b)-1)/(b))

static const int B  = 32;
static const int C  = 256;
static const int NZ = 225;   // 15*15
static const int NX = 961;   // 31*31
static const int KDIM = 2304; // C*9

// ---------------- scratch (device globals; no cudaMalloc allowed) ----------
__device__ float g_attnA[32 * 256 * 256];
__device__ float g_attnB[32 * 256 * 256];
__device__ float g_featZ[32 * 256 * 225];
__device__ float g_featX[32 * 256 * 961];
__device__ float g_off  [32 * 18  * 961];
__device__ float g_col  [2304 * 32 * 1024];   // padded im2col (302 MB)
__device__ float g_wr   [256 * 2304];         // tf32-rounded weights
__device__ float g_hi   [32 * 256 * 976];     // tf32 split hi, K padded
__device__ float g_lo   [32 * 256 * 976];     // tf32 split lo, K padded

// ======================= PTX helpers =======================================
__device__ __forceinline__ uint32_t smem_u32(const void* p) {
    uint32_t a;
    asm("{ .reg .u64 t; cvta.to.shared.u64 t, %1; cvt.u32.u64 %0, t; }" : "=r"(a) : "l"(p));
    return a;
}
__device__ __forceinline__ void cpa16(uint32_t dst, const void* src) {
    asm volatile("cp.async.cg.shared.global [%0], [%1], 16;" :: "r"(dst), "l"(src));
}
__device__ __forceinline__ float round_tf32(float v) {
    uint32_t r;
    asm("cvt.rna.tf32.f32 %0, %1;" : "=r"(r) : "f"(v));
    return __uint_as_float(r);
}
__device__ __forceinline__ void mma_tf32(float& c0, float& c1, float& c2, float& c3,
                                         uint32_t a0, uint32_t a1, uint32_t a2, uint32_t a3,
                                         uint32_t b0, uint32_t b1) {
    asm volatile(
        "mma.sync.aligned.m16n8k8.row.col.f32.tf32.tf32.f32 "
        "{%0,%1,%2,%3},{%4,%5,%6,%7},{%8,%9},{%0,%1,%2,%3};"
        : "+f"(c0), "+f"(c1), "+f"(c2), "+f"(c3)
        : "r"(a0), "r"(a1), "r"(a2), "r"(a3), "r"(b0), "r"(b1));
}

// ---------------------------------------------------------------------------
// split input into tf32 hi/lo pair, K padded to Kpad with zeros
// ---------------------------------------------------------------------------
__global__ __launch_bounds__(256) void splitf_kernel(const float* __restrict__ in,
                                                     float* __restrict__ hi,
                                                     float* __restrict__ lo,
                                                     int K, int Kpad, int total) {
    int i = blockIdx.x * 256 + threadIdx.x;
    if (i >= total) return;
    int bc = i / Kpad, k = i - bc * Kpad;
    float v = (k < K) ? in[(size_t)bc * K + k] : 0.f;
    float h = round_tf32(v);
    hi[i] = h;
    lo[i] = round_tf32(v - h);
}

// ---------------------------------------------------------------------------
// gram via 3xTF32: E[b] = F[b] * F[b]^T, K pre-padded (mult of 8)
// CTA 128x128, BK=8, cp.async double-buffered, 8 warps (2M x 4N)
// ---------------------------------------------------------------------------
__global__ __launch_bounds__(256) void gram_mma3_kernel(const float* __restrict__ hi,
                                                        const float* __restrict__ lo,
                                                        float* __restrict__ E, int Kpad) {
    __shared__ float Ah[2][1536], Al[2][1536], Bh[2][1536], Bl[2][1536];
    int b = blockIdx.z;
    int c0 = blockIdx.y * 128, d0 = blockIdx.x * 128;
    const size_t fb = (size_t)b * C * Kpad;
    int tid = threadIdx.x;
    int wid = tid >> 5, lane = tid & 31;
    int g = lane >> 2, t = lane & 3;
    int warpM = wid >> 2, warpN = wid & 3;

    uint32_t ahU = smem_u32(&Ah[0][0]);
    uint32_t alU = smem_u32(&Al[0][0]);
    uint32_t bhU = smem_u32(&Bh[0][0]);
    uint32_t blU = smem_u32(&Bl[0][0]);

    int lrow = tid >> 1, lhalf = tid & 1;
    auto load_stage = [&](int stg, int k0) {
        uint32_t doff = stg * 6144 + (lrow * 12 + lhalf * 4) * 4;
        const size_t sA = fb + (size_t)(c0 + lrow) * Kpad + k0 + lhalf * 4;
        const size_t sB = fb + (size_t)(d0 + lrow) * Kpad + k0 + lhalf * 4;
        cpa16(ahU + doff, hi + sA);
        cpa16(alU + doff, lo + sA);
        cpa16(bhU + doff, hi + sB);
        cpa16(blU + doff, lo + sB);
    };

    float acc[4][4][4];
#pragma unroll
    for (int i = 0; i < 4; i++)
#pragma unroll
        for (int j = 0; j < 4; j++)
#pragma unroll
            for (int r = 0; r < 4; r++) acc[i][j][r] = 0.f;

    const int ITERS = Kpad / 8;
    load_stage(0, 0);
    asm volatile("cp.async.commit_group;" ::: "memory");

    for (int it = 0; it < ITERS; it++) {
        int cur = it & 1;
        if (it + 1 < ITERS) load_stage(cur ^ 1, (it + 1) * 8);
        asm volatile("cp.async.commit_group;" ::: "memory");
        asm volatile("cp.async.wait_group 1;" ::: "memory");
        __syncthreads();

        const float* A0h = &Ah[cur][0];
        const float* A0l = &Al[cur][0];
        const float* B0h = &Bh[cur][0];
        const float* B0l = &Bl[cur][0];

        uint32_t ah[4][4], al[4][4];
#pragma unroll
        for (int mt = 0; mt < 4; mt++) {
            int m = warpM * 64 + mt * 16 + g;
            ah[mt][0] = __float_as_uint(A0h[m * 12 + t]);
            ah[mt][1] = __float_as_uint(A0h[(m + 8) * 12 + t]);
            ah[mt][2] = __float_as_uint(A0h[m * 12 + t + 4]);
            ah[mt][3] = __float_as_uint(A0h[(m + 8) * 12 + t + 4]);
            al[mt][0] = __float_as_uint(A0l[m * 12 + t]);
            al[mt][1] = __float_as_uint(A0l[(m + 8) * 12 + t]);
            al[mt][2] = __float_as_uint(A0l[m * 12 + t + 4]);
            al[mt][3] = __float_as_uint(A0l[(m + 8) * 12 + t + 4]);
        }
        uint32_t bh[4][2], bl[4][2];
#pragma unroll
        for (int nt = 0; nt < 4; nt++) {
            int n = warpN * 32 + nt * 8 + g;
            bh[nt][0] = __float_as_uint(B0h[n * 12 + t]);
            bh[nt][1] = __float_as_uint(B0h[n * 12 + t + 4]);
            bl[nt][0] = __float_as_uint(B0l[n * 12 + t]);
            bl[nt][1] = __float_as_uint(B0l[n * 12 + t + 4]);
        }
#pragma unroll
        for (int mt = 0; mt < 4; mt++)
#pragma unroll
            for (int nt = 0; nt < 4; nt++) {
                mma_tf32(acc[mt][nt][0], acc[mt][nt][1], acc[mt][nt][2], acc[mt][nt][3],
                         ah[mt][0], ah[mt][1], ah[mt][2], ah[mt][3],
                         bh[nt][0], bh[nt][1]);
                mma_tf32(acc[mt][nt][0], acc[mt][nt][1], acc[mt][nt][2], acc[mt][nt][3],
                         ah[mt][0], ah[mt][1], ah[mt][2], ah[mt][3],
                         bl[nt][0], bl[nt][1]);
                mma_tf32(acc[mt][nt][0], acc[mt][nt][1], acc[mt][nt][2], acc[mt][nt][3],
                         al[mt][0], al[mt][1], al[mt][2], al[mt][3],
                         bh[nt][0], bh[nt][1]);
            }
        __syncthreads();
    }

    float* Eb = E + (size_t)b * C * C;
#pragma unroll
    for (int mt = 0; mt < 4; mt++) {
        int m = c0 + warpM * 64 + mt * 16 + g;
#pragma unroll
        for (int nt = 0; nt < 4; nt++) {
            int n = d0 + warpN * 32 + nt * 8 + t * 2;
            Eb[(size_t)m * C + n]           = acc[mt][nt][0];
            Eb[(size_t)m * C + n + 1]       = acc[mt][nt][1];
            Eb[(size_t)(m + 8) * C + n]     = acc[mt][nt][2];
            Eb[(size_t)(m + 8) * C + n + 1] = acc[mt][nt][3];
        }
    }
}

// ---------------------------------------------------------------------------
// softmax of (rowmax - e) == exp(rowmin - e)/sum  (shuffle reductions)
// ---------------------------------------------------------------------------
__global__ __launch_bounds__(256) void attn_softmax_kernel(float* __restrict__ E) {
    int row = blockIdx.x;
    float* e = E + (size_t)row * 256;
    int t = threadIdx.x;
    int warp = t >> 5, lane = t & 31;
    __shared__ float sm[16];
    float v = e[t];
    float m = v;
#pragma unroll
    for (int s = 16; s > 0; s >>= 1) m = fminf(m, __shfl_xor_sync(0xffffffffu, m, s));
    if (lane == 0) sm[warp] = m;
    __syncthreads();
    float emin = fminf(fminf(fminf(sm[0], sm[1]), fminf(sm[2], sm[3])),
                       fminf(fminf(sm[4], sm[5]), fminf(sm[6], sm[7])));
    float p = expf(emin - v);
    float sum = p;
#pragma unroll
    for (int s = 16; s > 0; s >>= 1) sum += __shfl_xor_sync(0xffffffffu, sum, s);
    if (lane == 0) sm[8 + warp] = sum;
    __syncthreads();
    float tot = (sm[8] + sm[9]) + (sm[10] + sm[11]) + (sm[12] + sm[13]) + (sm[14] + sm[15]);
    e[t] = p / tot;
}

// ---------------------------------------------------------------------------
// cam_use via tf32 MMA: O[b] = gamma * A[b] @ F[b] + F[b]
// CTA 128x128, BK=8, A via cp.async double-buffer, B via guarded LDG+STS
// ---------------------------------------------------------------------------
__global__ __launch_bounds__(256) void camuse_mma_kernel(const float* __restrict__ A,
                                                         const float* __restrict__ F,
                                                         float* __restrict__ O, int N,
                                                         const float* __restrict__ gamma) {
    __shared__ float sA[2][1536];    // 128 x 8 (stride 12)
    __shared__ float sB[2][1088];    // 8 x 128 (stride 136)
    int b = blockIdx.z;
    int m0 = blockIdx.y * 128, n0 = blockIdx.x * 128;
    const float* Ab = A + (size_t)b * C * C;
    const float* Fb = F + (size_t)b * C * N;
    int tid = threadIdx.x;
    int wid = tid >> 5, lane = tid & 31;
    int g = lane >> 2, t = lane & 3;
    int warpM = wid >> 2, warpN = wid & 3;

    uint32_t sAu = smem_u32(&sA[0][0]);
    int lrow = tid >> 1, lhalf = tid & 1;

    auto load_stage = [&](int stg, int k0) {
        // A: cp.async
        cpa16(sAu + stg * 6144 + (lrow * 12 + lhalf * 4) * 4,
              Ab + (size_t)(m0 + lrow) * C + k0 + lhalf * 4);
        // B: guarded LDG + STS (rounded to tf32 rna)
#pragma unroll
        for (int i = 0; i < 4; i++) {
            int idx = tid + i * 256;
            int r = idx >> 7, cc = idx & 127;
            int n = n0 + cc;
            sB[stg][r * 136 + cc] = (n < N) ? round_tf32(Fb[(size_t)(k0 + r) * N + n]) : 0.f;
        }
    };

    float acc[4][4][4];
#pragma unroll
    for (int i = 0; i < 4; i++)
#pragma unroll
        for (int j = 0; j < 4; j++)
#pragma unroll
            for (int r = 0; r < 4; r++) acc[i][j][r] = 0.f;

    const int ITERS = C / 8;   // 32
    load_stage(0, 0);
    asm volatile("cp.async.commit_group;" ::: "memory");

    for (int it = 0; it < ITERS; it++) {
        int cur = it & 1;
        if (it + 1 < ITERS) load_stage(cur ^ 1, (it + 1) * 8);
        asm volatile("cp.async.commit_group;" ::: "memory");
        asm volatile("cp.async.wait_group 1;" ::: "memory");
        __syncthreads();

        const float* A0 = &sA[cur][0];
        const float* B0 = &sB[cur][0];
        uint32_t af[4][4];
#pragma unroll
        for (int mt = 0; mt < 4; mt++) {
            int m = warpM * 64 + mt * 16 + g;
            af[mt][0] = __float_as_uint(A0[m * 12 + t]);
            af[mt][1] = __float_as_uint(A0[(m + 8) * 12 + t]);
            af[mt][2] = __float_as_uint(A0[m * 12 + t + 4]);
            af[mt][3] = __float_as_uint(A0[(m + 8) * 12 + t + 4]);
        }
        uint32_t bf[4][2];
#pragma unroll
        for (int nt = 0; nt < 4; nt++) {
            int n = warpN * 32 + nt * 8 + g;
            bf[nt][0] = __float_as_uint(B0[t * 136 + n]);
            bf[nt][1] = __float_as_uint(B0[(t + 4) * 136 + n]);
        }
#pragma unroll
        for (int mt = 0; mt < 4; mt++)
#pragma unroll
            for (int nt = 0; nt < 4; nt++)
                mma_tf32(acc[mt][nt][0], acc[mt][nt][1], acc[mt][nt][2], acc[mt][nt][3],
                         af[mt][0], af[mt][1], af[mt][2], af[mt][3],
                         bf[nt][0], bf[nt][1]);
        __syncthreads();
    }

    float gm = gamma[0];
#pragma unroll
    for (int mt = 0; mt < 4; mt++) {
        int m = m0 + warpM * 64 + mt * 16 + g;
#pragma unroll
        for (int nt = 0; nt < 4; nt++) {
            int n = n0 + warpN * 32 + nt * 8 + t * 2;
            if (n < N) {
                O[((size_t)b * C + m) * N + n] = gm * acc[mt][nt][0] + Fb[(size_t)m * N + n];
                O[((size_t)b * C + m + 8) * N + n] = gm * acc[mt][nt][2] + Fb[(size_t)(m + 8) * N + n];
                if (n + 1 < N) {
                    O[((size_t)b * C + m) * N + n + 1] = gm * acc[mt][nt][1] + Fb[(size_t)m * N + n + 1];
                    O[((size_t)b * C + m + 8) * N + n + 1] = gm * acc[mt][nt][3] + Fb[(size_t)(m + 8) * N + n + 1];
                }
            }
        }
    }
}

// ---------------------------------------------------------------------------
// offset conv: 3x3, C -> 18, pad 1.  grid (ntile, 18, B), 128 threads
// ---------------------------------------------------------------------------
__global__ __launch_bounds__(128) void offconv_kernel(const float* __restrict__ feat,
                                                      const float* __restrict__ woff,
                                                      const float* __restrict__ boff,
                                                      float* __restrict__ off,
                                                      int H, int W) {
    __shared__ float sw[2304];
    int ch = blockIdx.y, b = blockIdx.z;
    const float* wp = woff + (size_t)ch * 2304;
    for (int i = threadIdx.x; i < 2304; i += 128) sw[i] = wp[i];
    __syncthreads();
    int N = H * W;
    int n = blockIdx.x * 128 + threadIdx.x;
    if (n >= N) return;
    int h = n / W, w = n % W;
    const float* fb = feat + (size_t)b * C * N;
    float acc = boff[ch];
    for (int c = 0; c < C; c++) {
        const float* fc = fb + (size_t)c * N;
        const float* swc = sw + c * 9;
#pragma unroll
        for (int ky = 0; ky < 3; ky++) {
            int y = h + ky - 1;
            if ((unsigned)y >= (unsigned)H) continue;
            const float* fr = fc + y * W;
#pragma unroll
            for (int kx = 0; kx < 3; kx++) {
                int x = w + kx - 1;
                if ((unsigned)x < (unsigned)W) acc += swc[ky * 3 + kx] * fr[x];
            }
        }
    }
    off[((size_t)b * 18 + ch) * N + n] = acc;
}

// ---------------------------------------------------------------------------
// bilinear deform sampling -> padded im2col, tf32-rounded values
// ---------------------------------------------------------------------------
__global__ __launch_bounds__(128) void sample_kernel(const float* __restrict__ feat,
                                                     const float* __restrict__ off,
                                                     float* __restrict__ col,
                                                     int H, int W, int Npad, int NtotPad) {
    int N = H * W;
    int b = blockIdx.z, k = blockIdx.y;
    int n = blockIdx.x * 128 + threadIdx.x;
    if (n >= N) return;
    int h = n / W, w = n % W;
    int ky = k / 3, kx = k % 3;
    float oy = off[((size_t)b * 18 + 2 * k) * N + n];
    float ox = off[((size_t)b * 18 + 2 * k + 1) * N + n];
    float py = (float)(h + ky - 1) + oy;
    float px = (float)(w + kx - 1) + ox;
    float y0f = floorf(py), x0f = floorf(px);
    float ly = py - y0f, lx = px - x0f;
    float Hm1 = (float)(H - 1), Wm1 = (float)(W - 1);

    float vy0 = (y0f >= 0.f && y0f <= Hm1) ? (1.f - ly) : 0.f;
    float vy1 = (y0f + 1.f >= 0.f && y0f + 1.f <= Hm1) ? ly : 0.f;
    float vx0 = (x0f >= 0.f && x0f <= Wm1) ? (1.f - lx) : 0.f;
    float vx1 = (x0f + 1.f >= 0.f && x0f + 1.f <= Wm1) ? lx : 0.f;
    int y0 = (int)fminf(fmaxf(y0f, 0.f), Hm1);
    int y1 = (int)fminf(fmaxf(y0f + 1.f, 0.f), Hm1);
    int x0 = (int)fminf(fmaxf(x0f, 0.f), Wm1);
    int x1 = (int)fminf(fmaxf(x0f + 1.f, 0.f), Wm1);

    int i00 = y0 * W + x0, i01 = y0 * W + x1, i10 = y1 * W + x0, i11 = y1 * W + x1;
    float w00 = vy0 * vx0, w01 = vy0 * vx1, w10 = vy1 * vx0, w11 = vy1 * vx1;

    const float* fb = feat + (size_t)b * C * N;
    float* cp = col + (size_t)k * NtotPad + (size_t)b * Npad + n;
    const size_t cstride = (size_t)9 * NtotPad;
    for (int c = 0; c < C; c++) {
        const float* fc = fb + (size_t)c * N;
        float v = w00 * fc[i00] + w01 * fc[i01] + w10 * fc[i10] + w11 * fc[i11];
        cp[(size_t)c * cstride] = round_tf32(v);
    }
}

// ---------------------------------------------------------------------------
// round W to tf32 once per scale
// ---------------------------------------------------------------------------
__global__ __launch_bounds__(256) void wround_kernel(const float* __restrict__ in,
                                                     float* __restrict__ out, int n) {
    int i = blockIdx.x * 256 + threadIdx.x;
    if (i < n) out[i] = round_tf32(in[i]);
}

// ---------------------------------------------------------------------------
// tf32 mma.sync GEMM:  out = W[256 x 2304] @ col[2304 x NtotPad]
// CTA 128x128, BK=16, 8 warps (2M x 4N), double-buffer cp.async
// grid (2, NTOT/128): m on x so sibling m-tiles share the col tile via L2
// ---------------------------------------------------------------------------
#define A_STRIDE 20
#define B_STRIDE 136

__global__ __launch_bounds__(256) void dconv_mma_kernel(const float* __restrict__ Wm,
                                                        const float* __restrict__ Bc,
                                                        float* __restrict__ out,
                                                        int Nsp, int NtotPad, int shift) {
    __shared__ float sA[2][128 * A_STRIDE];
    __shared__ float sB[2][16 * B_STRIDE];

    int tid = threadIdx.x;
    int wid = tid >> 5, lane = tid & 31;
    int g = lane >> 2, t = lane & 3;
    int warpM = wid >> 2;
    int warpN = wid & 3;

    int m0 = blockIdx.x * 128;
    int n0 = blockIdx.y * 128;
    int bb = n0 >> shift;
    int nl0 = n0 & ((1 << shift) - 1);

    uint32_t sAu = smem_u32(&sA[0][0]);
    uint32_t sBu = smem_u32(&sB[0][0]);

    auto load_stage = [&](int stg, int k0) {
        uint32_t aBase = sAu + stg * (128 * A_STRIDE * 4);
        uint32_t bBase = sBu + stg * (16 * B_STRIDE * 4);
#pragma unroll
        for (int i = 0; i < 2; i++) {
            int q = tid + i * 256;
            int row = q >> 2, c16 = q & 3;
            cpa16(aBase + (row * A_STRIDE + c16 * 4) * 4,
                  Wm + (size_t)(m0 + row) * KDIM + k0 + c16 * 4);
        }
#pragma unroll
        for (int i = 0; i < 2; i++) {
            int q = tid + i * 256;
            int row = q >> 5, c = q & 31;
            cpa16(bBase + (row * B_STRIDE + c * 4) * 4,
                  Bc + (size_t)(k0 + row) * NtotPad + n0 + c * 4);
        }
    };

    float acc[4][4][4];
#pragma unroll
    for (int i = 0; i < 4; i++)
#pragma unroll
        for (int j = 0; j < 4; j++)
#pragma unroll
            for (int r = 0; r < 4; r++) acc[i][j][r] = 0.f;

    const int ITERS = KDIM / 16;   // 144
    load_stage(0, 0);
    asm volatile("cp.async.commit_group;" ::: "memory");

    for (int it = 0; it < ITERS; ++it) {
        int cur = it & 1;
        if (it + 1 < ITERS) load_stage(cur ^ 1, (it + 1) * 16);
        asm volatile("cp.async.commit_group;" ::: "memory");
        asm volatile("cp.async.wait_group 1;" ::: "memory");
        __syncthreads();

        const float* A0 = &sA[cur][0];
        const float* B0 = &sB[cur][0];
#pragma unroll
        for (int ks = 0; ks < 2; ks++) {
            int kb = ks * 8;
            uint32_t af[4][4];
#pragma unroll
            for (int mt = 0; mt < 4; mt++) {
                int m = warpM * 64 + mt * 16 + g;
                af[mt][0] = __float_as_uint(A0[m * A_STRIDE + kb + t]);
                af[mt][1] = __float_as_uint(A0[(m + 8) * A_STRIDE + kb + t]);
                af[mt][2] = __float_as_uint(A0[m * A_STRIDE + kb + t + 4]);
                af[mt][3] = __float_as_uint(A0[(m + 8) * A_STRIDE + kb + t + 4]);
            }
            uint32_t bf[4][2];
#pragma unroll
            for (int nt = 0; nt < 4; nt++) {
                int n = warpN * 32 + nt * 8 + g;
                bf[nt][0] = __float_as_uint(B0[(kb + t) * B_STRIDE + n]);
                bf[nt][1] = __float_as_uint(B0[(kb + t + 4) * B_STRIDE + n]);
            }
#pragma unroll
            for (int mt = 0; mt < 4; mt++)
#pragma unroll
                for (int nt = 0; nt < 4; nt++)
                    mma_tf32(acc[mt][nt][0], acc[mt][nt][1], acc[mt][nt][2], acc[mt][nt][3],
                             af[mt][0], af[mt][1], af[mt][2], af[mt][3],
                             bf[nt][0], bf[nt][1]);
        }
        __syncthreads();
    }

#pragma unroll
    for (int mt = 0; mt < 4; mt++) {
        int m = m0 + warpM * 64 + mt * 16 + g;
        float* r0 = out + ((size_t)bb * C + m) * Nsp;
        float* r1 = out + ((size_t)bb * C + m + 8) * Nsp;
#pragma unroll
        for (int nt = 0; nt < 4; nt++) {
            int n = nl0 + warpN * 32 + nt * 8 + t * 2;
            if (n < Nsp) {
                r0[n] = acc[mt][nt][0];
                r1[n] = acc[mt][nt][2];
                if (n + 1 < Nsp) {
                    r0[n + 1] = acc[mt][nt][1];
                    r1[n + 1] = acc[mt][nt][3];
                }
            }
        }
    }
}

// ---------------------------------------------------------------------------
extern "C" void kernel_launch(void* const* d_in, const int* in_sizes, int n_in,
                              void* d_out, int out_size) {
    const float *Z[3], *X[3], *OW[3], *OB[3], *DW[3], *G[3];
    int nz = 0, nx = 0, nw = 0, nb = 0, nd = 0, ng = 0;
    for (int i = 0; i < n_in; i++) {
        switch (in_sizes[i]) {
            case 1843200: Z[nz++]  = (const float*)d_in[i]; break;
            case 7872512: X[nx++]  = (const float*)d_in[i]; break;
            case 41472:   OW[nw++] = (const float*)d_in[i]; break;
            case 18:      OB[nb++] = (const float*)d_in[i]; break;
            case 589824:  DW[nd++] = (const float*)d_in[i]; break;
            case 1:       G[ng++]  = (const float*)d_in[i]; break;
            default: break;
        }
    }

    float *attnA, *attnB, *featZ, *featX, *offb, *colb, *wrb, *hib, *lob;
    cudaGetSymbolAddress((void**)&attnA, g_attnA);
    cudaGetSymbolAddress((void**)&attnB, g_attnB);
    cudaGetSymbolAddress((void**)&featZ, g_featZ);
    cudaGetSymbolAddress((void**)&featX, g_featX);
    cudaGetSymbolAddress((void**)&offb,  g_off);
    cudaGetSymbolAddress((void**)&colb,  g_col);
    cudaGetSymbolAddress((void**)&wrb,   g_wr);
    cudaGetSymbolAddress((void**)&hib,   g_hi);
    cudaGetSymbolAddress((void**)&lob,   g_lo);

    float* outZ = (float*)d_out;
    float* outX = outZ + (size_t)3 * B * C * NZ;

    const int NPAD_Z = 256,  SH_Z = 8;
    const int NPAD_X = 1024, SH_X = 10;
    const int NTOT_Z = B * NPAD_Z;   // 8192
    const int NTOT_X = B * NPAD_X;   // 32768
    const int KP_Z = 240;            // 225 -> 240 (mult of 16)
    const int KP_X = 976;            // 961 -> 976 (mult of 16)
    const int TOT_Z = B * C * KP_Z;  // 1966080
    const int TOT_X = B * C * KP_X;  // 7995392

    for (int i = 0; i < 3; i++) {
        // --- channel attention (gram via pipelined 3xTF32) ---
        splitf_kernel<<<CDIV(TOT_Z, 256), 256>>>(Z[i], hib, lob, NZ, KP_Z, TOT_Z);
        gram_mma3_kernel<<<dim3(2, 2, B), 256>>>(hib, lob, attnA, KP_Z);
        attn_softmax_kernel<<<B * C, 256>>>(attnA);
        splitf_kernel<<<CDIV(TOT_X, 256), 256>>>(X[i], hib, lob, NX, KP_X, TOT_X);
        gram_mma3_kernel<<<dim3(2, 2, B), 256>>>(hib, lob, attnB, KP_X);
        attn_softmax_kernel<<<B * C, 256>>>(attnB);

        // --- cam_use (cross attention) via pipelined tf32 MMA ---
        camuse_mma_kernel<<<dim3(2, 2, B), 256>>>(attnB, Z[i], featZ, NZ, G[i]);
        camuse_mma_kernel<<<dim3(8, 2, B), 256>>>(attnA, X[i], featX, NX, G[i]);

        wround_kernel<<<CDIV(256 * KDIM, 256), 256>>>(DW[i], wrb, 256 * KDIM);

        // --- z branch ---
        offconv_kernel<<<dim3(CDIV(NZ, 128), 18, B), 128>>>(featZ, OW[i], OB[i], offb, 15, 15);
        sample_kernel<<<dim3(CDIV(NZ, 128), 9, B), 128>>>(featZ, offb, colb, 15, 15, NPAD_Z, NTOT_Z);
        dconv_mma_kernel<<<dim3(2, NTOT_Z / 128), 256>>>(wrb, colb,
                                                         outZ + (size_t)i * B * C * NZ,
                                                         NZ, NTOT_Z, SH_Z);
        // --- x branch ---
        offconv_kernel<<<dim3(CDIV(NX, 128), 18, B), 128>>>(featX, OW[i], OB[i], offb, 31, 31);
        sample_kernel<<<dim3(CDIV(NX, 128), 9, B), 128>>>(featX, offb, colb, 31, 31, NPAD_X, NTOT_X);
        dconv_mma_kernel<<<dim3(2, NTOT_X / 128), 256>>>(wrb, colb,
                                                         outX + (size_t)i * B * C * NX,
                                                         NX, NTOT_X, SH_X);
    }
    (void)out_size;
}